// round 13
// baseline (speedup 1.0000x reference)
#include <cuda_runtime.h>
#include <cuda_fp16.h>
#include <cstdint>

#define TT 1024
#define BB 64
#define HH 512
#define RR (TT*BB)              // 65536 rows
#define RES ((size_t)RR*HH)
#define BH (BB*HH)
#define NTILES 8192             // 512 row-blocks x 16 ncb-blocks

// ---------------- device scratch ----------------
__device__ __half g_xh[(size_t)RR*512];      // x in fp16 (natural order)
__device__ __half g_hy0h[(size_t)RR*512];    // layer-0 hy in fp16 (natural order)
__device__ __half g_wp[2][2048*512];         // gate-permuted rows (p=4h+gate), natural k
__device__ float  g_hhp[2][BB*2048];         // h0@Whh^T + b_ih + b_hh, cols p=4h+gate

// ---------------- helpers ----------------
__device__ __forceinline__ uint32_t smem_u32(const void* p){
    uint32_t a; asm("{ .reg .u64 t; cvta.to.shared.u64 t, %1; cvt.u32.u64 %0, t; }" : "=r"(a) : "l"(p)); return a;
}
__device__ __forceinline__ float tanha(float x){ float r; asm("tanh.approx.f32 %0,%1;" : "=f"(r):"f"(x)); return r; }

__device__ __forceinline__ void cpa16(uint32_t dst, const void* src){
    asm volatile("cp.async.cg.shared.global [%0], [%1], 16;" :: "r"(dst), "l"(src) : "memory");
}
#define CP_COMMIT() asm volatile("cp.async.commit_group;" ::: "memory")

__device__ __forceinline__ void mma16(float* c, const uint32_t* a, const uint32_t* b){
    asm volatile("mma.sync.aligned.m16n8k16.row.col.f32.f16.f16.f32 "
                 "{%0,%1,%2,%3}, {%4,%5,%6,%7}, {%8,%9}, {%0,%1,%2,%3};"
                 : "+f"(c[0]),"+f"(c[1]),"+f"(c[2]),"+f"(c[3])
                 : "r"(a[0]),"r"(a[1]),"r"(a[2]),"r"(a[3]), "r"(b[0]),"r"(b[1]));
}
__device__ __forceinline__ void ldsm4(uint32_t* r, uint32_t addr){
    asm volatile("ldmatrix.sync.aligned.m8n8.x4.shared.b16 {%0,%1,%2,%3}, [%4];"
                 : "=r"(r[0]),"=r"(r[1]),"=r"(r[2]),"=r"(r[3]) : "r"(addr));
}
__device__ __forceinline__ uint32_t h2u(const __half2 h){
    union { __half2 h2; uint32_t u; } cv; cv.h2 = h; return cv.u;
}

// natural-order pack: 16 floats -> 16 halves (2 uint4)
__device__ __forceinline__ void pack_nat(const float4 f0, const float4 f1,
                                         const float4 f2, const float4 f3, uint4* o){
    o[0] = make_uint4(h2u(__floats2half2_rn(f0.x,f0.y)), h2u(__floats2half2_rn(f0.z,f0.w)),
                      h2u(__floats2half2_rn(f1.x,f1.y)), h2u(__floats2half2_rn(f1.z,f1.w)));
    o[1] = make_uint4(h2u(__floats2half2_rn(f2.x,f2.y)), h2u(__floats2half2_rn(f2.z,f2.w)),
                      h2u(__floats2half2_rn(f3.x,f3.y)), h2u(__floats2half2_rn(f3.z,f3.w)));
}

// ---------------- prep kernels ----------------
__global__ void conv_x(const float* __restrict__ x){
    int task = blockIdx.x*256 + threadIdx.x;        // row*32 + grp
    if (task >= RR*32) return;
    int row = task >> 5, grp = task & 31;
    const float4* s = (const float4*)(x + (size_t)row*512 + grp*16);
    uint4 o[2];
    pack_nat(s[0], s[1], s[2], s[3], o);
    uint4* d = (uint4*)(g_xh + (size_t)row*512 + grp*16);
    d[0] = o[0]; d[1] = o[1];
}

__global__ void conv_w(const float* __restrict__ wih0, const float* __restrict__ wih1){
    int p = blockIdx.x*8 + (threadIdx.x>>5), l = blockIdx.y, grp = threadIdx.x&31;
    const float* w = l ? wih1 : wih0;
    int grow = ((p&3)<<9) + (p>>2);
    const float4* s = (const float4*)(w + (size_t)grow*512 + grp*16);
    uint4 o[2];
    pack_nat(s[0], s[1], s[2], s[3], o);
    uint4* d = (uint4*)(&g_wp[l][(size_t)p*512 + grp*16]);
    d[0] = o[0]; d[1] = o[1];
}

// tiled: block = 16 p-rows x 64 b; h0 k-slice staged in smem transposed [k][b]
__global__ void __launch_bounds__(1024,1) prep_hh(
        const float* __restrict__ h0,
        const float* __restrict__ whh0, const float* __restrict__ bhh0, const float* __restrict__ bih0,
        const float* __restrict__ whh1, const float* __restrict__ bhh1, const float* __restrict__ bih1){
    __shared__ float sh[128][65];
    int l = blockIdx.y;
    int tid = threadIdx.x;
    int pi = tid >> 6, b = tid & 63;
    int p = blockIdx.x*16 + pi;
    const float* whh = l ? whh1 : whh0;
    const float* bhh = l ? bhh1 : bhh0;
    const float* bih = l ? bih1 : bih0;
    int grow = ((p&3)<<9) + (p>>2);
    const float* wr = whh + (size_t)grow*512;
    float acc = 0.f;
    for (int kb = 0; kb < 4; kb++){
        #pragma unroll
        for (int i = 0; i < 2; i++){
            int f4 = tid*2 + i;                 // 0..2047
            int bb = f4 >> 5, kq = f4 & 31;
            float4 v = *(const float4*)(h0 + (size_t)(l*64+bb)*512 + kb*128 + kq*4);
            sh[kq*4+0][bb] = v.x; sh[kq*4+1][bb] = v.y;
            sh[kq*4+2][bb] = v.z; sh[kq*4+3][bb] = v.w;
        }
        __syncthreads();
        const float4* wv = (const float4*)(wr + kb*128);
        #pragma unroll 8
        for (int k4 = 0; k4 < 32; k4++){
            float4 w = wv[k4];
            acc += w.x*sh[k4*4+0][b] + w.y*sh[k4*4+1][b]
                 + w.z*sh[k4*4+2][b] + w.w*sh[k4*4+3][b];
        }
        __syncthreads();
    }
    g_hhp[l][b*2048 + p] = acc + bhh[grow] + bih[grow];
}

// ---------------- persistent fused GEMM + LSTM epilogue ----------------
// CTA tile 128x128, 4 warps (2m x 2n), warp tile 64x64, K-chunk 64, 3-stage ring
// running CONTINUOUSLY across tiles; epilogue overlapped with next tile's loads.
#define STG_B    16384                 // B offset inside a stage (A = 128*128B)
#define STAGE_SZ 32768
#define EP_OFF   (3*STAGE_SZ)          // 98304: epilogue staging (half tile)
#define EP_SZ    10240                 // fp32 half: [128][20] floats
#define SMEM_TOT (EP_OFF + EP_SZ)      // 108544

__global__ void __launch_bounds__(128,2)
lstm_gemm(const __half* __restrict__ Ah, const __half* __restrict__ Bh,
          const float* __restrict__ hhp, const float* __restrict__ c0l,
          float* __restrict__ outf, __half* __restrict__ outh,
          float* __restrict__ lasth, float* __restrict__ lastc, int G)
{
    extern __shared__ char smem[];
    const uint32_t sb = smem_u32(smem);
    const int tid = threadIdx.x, wid = tid>>5, lane = tid&31;
    const int g = lane>>2, t = lane&3;
    const int wm = wid&1, wn = wid>>1;          // 2 x 2 warp grid, warp tile 64x64
    const int lr = tid>>3, lc = tid&7;
    const uint32_t stOff = (uint32_t)(lr*128 + ((lc ^ (lr&7))<<4));

    auto issue = [&](int stage, const __half* as, const __half* bs){
        uint32_t base = sb + stage*STAGE_SZ + stOff;
#pragma unroll
        for (int j = 0; j < 8; j++) cpa16(base + j*2048, as + j*(16*512));
#pragma unroll
        for (int j = 0; j < 8; j++) cpa16(base + STG_B + j*2048, bs + j*(16*512));
        CP_COMMIT();
    };

    // --- ldmatrix per-lane constants ---
    const int lrow = lane&7, grp = lane>>3;
    const uint32_t aBase = (uint32_t)((wm*64 + (grp&1)*8 + lrow)*128);
    const uint32_t bBase = (uint32_t)(STG_B + (wn*64 + (grp>>1)*8 + lrow)*128);
    const int aCsel = grp>>1, bCsel = grp&1;

    int tile = blockIdx.x;
    if (tile >= NTILES) return;
    const __half* curA = Ah + (size_t)(((tile>>4)*128) + lr)*512 + lc*8;
    const __half* curB = Bh + (size_t)(((tile&15)*128) + lr)*512 + lc*8;
    issue(0, curA, curB);
    issue(1, curA + 64, curB + 64);
    int ci = 0;   // global chunk counter (consume index); stage = ci%3

    float* epS = (float*)(smem + EP_OFF);
    __half* epH = (__half*)(smem + EP_OFF);

    while (tile < NTILES){
        const int row0 = (tile>>4)*128, ncb = (tile&15)*128, hbase = ncb>>2;
        const bool tailCTA = (row0 == RR - 128);
        int ntile = tile + G; if (ntile >= NTILES) ntile = tile;   // safe clamp
        const __half* nxtA = Ah + (size_t)(((ntile>>4)*128) + lr)*512 + lc*8;
        const __half* nxtB = Bh + (size_t)(((ntile&15)*128) + lr)*512 + lc*8;

        float acc[4][8][4];
#pragma unroll
        for (int a = 0; a < 4; a++)
#pragma unroll
            for (int b = 0; b < 8; b++)
#pragma unroll
                for (int c = 0; c < 4; c++) acc[a][b][c] = 0.f;

        for (int kc = 0; kc < 8; kc++){
            asm volatile("cp.async.wait_group 1;" ::: "memory");
            __syncthreads();
            {   // issue chunk ci+2 (2 ahead; crosses into next tile at kc>=6)
                int k2 = kc + 2;
                const __half *as, *bs;
                if (k2 < 8){ as = curA + k2*64;     bs = curB + k2*64; }
                else       { as = nxtA + (k2-8)*64; bs = nxtB + (k2-8)*64; }
                issue((ci+2)%3, as, bs);
            }
            const uint32_t st = sb + (ci%3)*STAGE_SZ;
#pragma unroll
            for (int ks = 0; ks < 4; ks++){
                const uint32_t va = (uint32_t)(((2*ks + aCsel) ^ lrow) << 4);
                const uint32_t vb = (uint32_t)(((2*ks + bCsel) ^ lrow) << 4);
                uint32_t a[4][4], b[8][2];
#pragma unroll
                for (int mt = 0; mt < 4; mt++)
                    ldsm4(a[mt], st + aBase + mt*2048 + va);
#pragma unroll
                for (int pr = 0; pr < 4; pr++){
                    uint32_t q[4];
                    ldsm4(q, st + bBase + pr*2048 + vb);
                    b[pr*2][0] = q[0]; b[pr*2][1] = q[1];
                    b[pr*2+1][0] = q[2]; b[pr*2+1][1] = q[3];
                }
#pragma unroll
                for (int mt = 0; mt < 4; mt++)
#pragma unroll
                    for (int nt = 0; nt < 8; nt++)
                        mma16(acc[mt][nt], a[mt], b[nt]);
            }
            ci++;
        }

        // ---- epilogue (overlaps next tile's in-flight cp.async) ----
#pragma unroll
        for (int h = 0; h < 2; h++){
            if (h) __syncthreads();     // protect EP buffer from previous half's reads
#pragma unroll
            for (int mt = 0; mt < 4; mt++){
#pragma unroll
                for (int nq = 0; nq < 4; nq++){
                    const int nt = h*4 + nq;
                    int rl0 = wm*64 + mt*16 + g;
                    int rl1 = rl0 + 8;
                    int pl  = wn*64 + nt*8 + 2*t;
                    const float2 hbE = *(const float2*)(hhp + (rl0&63)*2048 + ncb + pl);
                    const float2 hbO = *(const float2*)(hhp + (rl1&63)*2048 + ncb + pl);
                    float d0 = acc[mt][nt][0] + hbE.x;
                    float d1 = acc[mt][nt][1] + hbE.y;
                    float d2 = acc[mt][nt][2] + hbO.x;
                    float d3 = acc[mt][nt][3] + hbO.y;
                    float s0 = (t&1) ? d0 : d2;  float r0 = __shfl_xor_sync(0xffffffffu, s0, 1);
                    float s1 = (t&1) ? d1 : d3;  float r1 = __shfl_xor_sync(0xffffffffu, s1, 1);
                    float ig, fg, gg, og; int rr;
                    if (!(t&1)){ ig = d0; fg = d1; gg = r0; og = r1; rr = rl0; }
                    else       { ig = r0; fg = r1; gg = d2; og = d3; rr = rl1; }
                    const int col = wn*8 + nq*2 + (t>>1);      // 0..15 within half
                    const int hl  = wn*16 + 8*h + nq*2 + (t>>1);
                    float c0v = c0l[(rr&63)*512 + hbase + hl];
                    float tf = tanha(0.5f*fg), ti = tanha(0.5f*ig);
                    float tg = tanha(gg),      to = tanha(0.5f*og);
                    float cy = (0.5f + 0.5f*tf)*c0v + (0.5f + 0.5f*ti)*tg;
                    float hy = (0.5f + 0.5f*to)*tanha(cy);
                    if (outf) epS[rr*20 + col] = hy;
                    else      epH[rr*24 + col] = __float2half_rn(hy);
                    if (tailCTA){
                        int grow_ = row0 + rr;
                        if (grow_ >= RR - BB){
                            int b = grow_ & 63;
                            lasth[b*512 + hbase + hl] = hy;
                            lastc[b*512 + hbase + hl] = cy;
                        }
                    }
                }
            }
            __syncthreads();
            if (outf){
#pragma unroll
                for (int i = 0; i < 4; i++){
                    int idx = tid + i*128;
                    int r = idx >> 2, j = idx & 3;
                    float4 v = *(const float4*)(epS + r*20 + j*4);
                    int hl = (j < 2) ? (8*h + j*4) : (16 + 8*h + (j-2)*4);
                    *(float4*)(outf + (size_t)(row0+r)*512 + hbase + hl) = v;
                }
            } else {
#pragma unroll
                for (int i = 0; i < 2; i++){
                    int idx = tid + i*128;
                    int r = idx >> 1, j = idx & 1;
                    uint4 v = *(const uint4*)(epH + r*24 + j*8);
                    *(uint4*)(outh + (size_t)(row0+r)*512 + hbase + j*16 + 8*h) = v;
                }
            }
        }

        curA = nxtA; curB = nxtB;
        tile += G;
    }
}

// ---------------- launch ----------------
extern "C" void kernel_launch(void* const* d_in, const int* in_sizes, int n_in,
                              void* d_out, int out_size)
{
    (void)in_sizes; (void)n_in; (void)out_size;
    const float* x    = (const float*)d_in[0];
    const float* h0   = (const float*)d_in[1];
    const float* c0   = (const float*)d_in[2];
    const float* wih0 = (const float*)d_in[3];
    const float* whh0 = (const float*)d_in[4];
    const float* bih0 = (const float*)d_in[5];
    const float* bhh0 = (const float*)d_in[6];
    const float* wih1 = (const float*)d_in[7];
    const float* whh1 = (const float*)d_in[8];
    const float* bih1 = (const float*)d_in[9];
    const float* bhh1 = (const float*)d_in[10];
    float* out = (float*)d_out;

    static __half* xh_p = nullptr; static __half* hy0h_p = nullptr;
    static __half* wp0_p = nullptr; static __half* wp1_p = nullptr;
    static float* hhp0_p = nullptr; static float* hhp1_p = nullptr;
    static int G = 0;
    if (!xh_p){
        cudaGetSymbolAddress((void**)&xh_p,   g_xh);
        cudaGetSymbolAddress((void**)&hy0h_p, g_hy0h);
        void* wp; cudaGetSymbolAddress(&wp, g_wp);
        wp0_p = (__half*)wp; wp1_p = wp0_p + 2048*512;
        void* hh; cudaGetSymbolAddress(&hh, g_hhp);
        hhp0_p = (float*)hh; hhp1_p = hhp0_p + BB*2048;
        cudaFuncSetAttribute(lstm_gemm, cudaFuncAttributeMaxDynamicSharedMemorySize, SMEM_TOT);
        int dev = 0, sms = 148;
        cudaGetDevice(&dev);
        cudaDeviceGetAttribute(&sms, cudaDevAttrMultiProcessorCount, dev);
        G = 2*sms;
    }

    conv_x<<<(RR*32 + 255)/256, 256>>>(x);
    conv_w<<<dim3(256,2), 256>>>(wih0, wih1);
    prep_hh<<<dim3(128,2), 1024>>>(h0, whh0, bhh0, bih0, whh1, bhh1, bih1);

    // layer 0: A = xh, B = wp0 -> hy0h (fp16), lasth[0], lastc[0]
    lstm_gemm<<<G, 128, SMEM_TOT>>>(xh_p, wp0_p, hhp0_p, c0,
                                    nullptr, hy0h_p,
                                    out + RES, out + RES + 2*(size_t)BH, G);
    // layer 1: A = hy0h, B = wp1 -> out (fp32), lasth[1], lastc[1]
    lstm_gemm<<<G, 128, SMEM_TOT>>>(hy0h_p, wp1_p, hhp1_p, c0 + BH,
                                    out, nullptr,
                                    out + RES + (size_t)BH, out + RES + 3*(size_t)BH, G);
}

// round 15
// speedup vs baseline: 1.0185x; 1.0185x over previous
#include <cuda_runtime.h>
#include <cuda_fp16.h>
#include <cstdint>

#define TT 1024
#define BB 64
#define HH 512
#define RR (TT*BB)              // 65536 rows
#define RES ((size_t)RR*HH)
#define BH (BB*HH)

// ---------------- device scratch ----------------
__device__ __half g_xh[(size_t)RR*512];      // x in fp16 (natural order)
__device__ __half g_hy0h[(size_t)RR*512];    // layer-0 hy in fp16 (natural order)
__device__ __half g_wp[2][2048*512];         // gate-permuted rows (p=4h+gate), natural k
__device__ float  g_hhp[2][BB*2048];         // h0@Whh^T + b_ih + b_hh, cols p=4h+gate

// ---------------- helpers ----------------
__device__ __forceinline__ uint32_t smem_u32(const void* p){
    uint32_t a; asm("{ .reg .u64 t; cvta.to.shared.u64 t, %1; cvt.u32.u64 %0, t; }" : "=r"(a) : "l"(p)); return a;
}
__device__ __forceinline__ float tanha(float x){ float r; asm("tanh.approx.f32 %0,%1;" : "=f"(r):"f"(x)); return r; }

__device__ __forceinline__ void cpa16(uint32_t dst, const void* src){
    asm volatile("cp.async.cg.shared.global [%0], [%1], 16;" :: "r"(dst), "l"(src) : "memory");
}

// mbarrier ops (sm_80 PTX, legal on plain sm_103 target)
#define MBAR_INIT(mb, c)  asm volatile("mbarrier.init.shared.b64 [%0], %1;" :: "r"(mb), "r"(c) : "memory")
#define MBAR_ARRIVE(mb)   asm volatile("{ .reg .b64 st; mbarrier.arrive.shared.b64 st, [%0]; }" :: "r"(mb) : "memory")
#define CPA_ARRIVE(mb)    asm volatile("cp.async.mbarrier.arrive.noinc.shared.b64 [%0];" :: "r"(mb) : "memory")

#define MBAR_WAIT(mb, par) do {                                                     \
    uint32_t _m=(uint32_t)(mb), _p=(uint32_t)(par), _d;                             \
    asm volatile("{ .reg .pred p; mbarrier.try_wait.parity.shared.b64 p, [%1], %2; selp.b32 %0,1,0,p; }" \
                 : "=r"(_d) : "r"(_m), "r"(_p) : "memory");                         \
    if(!_d){ asm volatile("{ .reg .pred P1; WL_%=: mbarrier.try_wait.parity.shared.b64 P1, [%0], %1, 0x989680; @P1 bra.uni WD_%=; bra.uni WL_%=; WD_%=: }" \
                 :: "r"(_m), "r"(_p) : "memory"); }                                 \
} while(0)

__device__ __forceinline__ void mma16(float* c, const uint32_t* a, const uint32_t* b){
    asm volatile("mma.sync.aligned.m16n8k16.row.col.f32.f16.f16.f32 "
                 "{%0,%1,%2,%3}, {%4,%5,%6,%7}, {%8,%9}, {%0,%1,%2,%3};"
                 : "+f"(c[0]),"+f"(c[1]),"+f"(c[2]),"+f"(c[3])
                 : "r"(a[0]),"r"(a[1]),"r"(a[2]),"r"(a[3]), "r"(b[0]),"r"(b[1]));
}
__device__ __forceinline__ void ldsm4(uint32_t* r, uint32_t addr){
    asm volatile("ldmatrix.sync.aligned.m8n8.x4.shared.b16 {%0,%1,%2,%3}, [%4];"
                 : "=r"(r[0]),"=r"(r[1]),"=r"(r[2]),"=r"(r[3]) : "r"(addr));
}
__device__ __forceinline__ uint32_t h2u(const __half2 h){
    union { __half2 h2; uint32_t u; } cv; cv.h2 = h; return cv.u;
}

// natural-order pack: 16 floats -> 16 halves (2 uint4)
__device__ __forceinline__ void pack_nat(const float4 f0, const float4 f1,
                                         const float4 f2, const float4 f3, uint4* o){
    o[0] = make_uint4(h2u(__floats2half2_rn(f0.x,f0.y)), h2u(__floats2half2_rn(f0.z,f0.w)),
                      h2u(__floats2half2_rn(f1.x,f1.y)), h2u(__floats2half2_rn(f1.z,f1.w)));
    o[1] = make_uint4(h2u(__floats2half2_rn(f2.x,f2.y)), h2u(__floats2half2_rn(f2.z,f2.w)),
                      h2u(__floats2half2_rn(f3.x,f3.y)), h2u(__floats2half2_rn(f3.z,f3.w)));
}

// ---------------- prep kernels ----------------
__global__ void conv_x(const float* __restrict__ x){
    int task = blockIdx.x*256 + threadIdx.x;        // row*32 + grp
    if (task >= RR*32) return;
    int row = task >> 5, grp = task & 31;
    const float4* s = (const float4*)(x + (size_t)row*512 + grp*16);
    uint4 o[2];
    pack_nat(s[0], s[1], s[2], s[3], o);
    uint4* d = (uint4*)(g_xh + (size_t)row*512 + grp*16);
    d[0] = o[0]; d[1] = o[1];
}

__global__ void conv_w(const float* __restrict__ wih0, const float* __restrict__ wih1){
    int p = blockIdx.x*8 + (threadIdx.x>>5), l = blockIdx.y, grp = threadIdx.x&31;
    const float* w = l ? wih1 : wih0;
    int grow = ((p&3)<<9) + (p>>2);
    const float4* s = (const float4*)(w + (size_t)grow*512 + grp*16);
    uint4 o[2];
    pack_nat(s[0], s[1], s[2], s[3], o);
    uint4* d = (uint4*)(&g_wp[l][(size_t)p*512 + grp*16]);
    d[0] = o[0]; d[1] = o[1];
}

// tiled: block = 16 p-rows x 64 b; h0 k-slice staged in smem transposed [k][b]
__global__ void __launch_bounds__(1024,1) prep_hh(
        const float* __restrict__ h0,
        const float* __restrict__ whh0, const float* __restrict__ bhh0, const float* __restrict__ bih0,
        const float* __restrict__ whh1, const float* __restrict__ bhh1, const float* __restrict__ bih1){
    __shared__ float sh[128][65];
    int l = blockIdx.y;
    int tid = threadIdx.x;
    int pi = tid >> 6, b = tid & 63;
    int p = blockIdx.x*16 + pi;
    const float* whh = l ? whh1 : whh0;
    const float* bhh = l ? bhh1 : bhh0;
    const float* bih = l ? bih1 : bih0;
    int grow = ((p&3)<<9) + (p>>2);
    const float* wr = whh + (size_t)grow*512;
    float acc = 0.f;
    for (int kb = 0; kb < 4; kb++){
        #pragma unroll
        for (int i = 0; i < 2; i++){
            int f4 = tid*2 + i;                 // 0..2047
            int bb = f4 >> 5, kq = f4 & 31;
            float4 v = *(const float4*)(h0 + (size_t)(l*64+bb)*512 + kb*128 + kq*4);
            sh[kq*4+0][bb] = v.x; sh[kq*4+1][bb] = v.y;
            sh[kq*4+2][bb] = v.z; sh[kq*4+3][bb] = v.w;
        }
        __syncthreads();
        const float4* wv = (const float4*)(wr + kb*128);
        #pragma unroll 8
        for (int k4 = 0; k4 < 32; k4++){
            float4 w = wv[k4];
            acc += w.x*sh[k4*4+0][b] + w.y*sh[k4*4+1][b]
                 + w.z*sh[k4*4+2][b] + w.w*sh[k4*4+3][b];
        }
        __syncthreads();
    }
    g_hhp[l][b*2048 + p] = acc + bhh[grow] + bih[grow];
}

// ---------------- fused GEMM + LSTM epilogue (mbarrier ring, no bar.sync) ----------------
// CTA tile 128x128, 4 warps (2m x 2n), warp tile 64x64, K-chunk 64, 3-stage mbarrier ring.
#define STG_B    16384                 // B offset inside a stage (A = 128*128B)
#define STAGE_SZ 32768
#define MB_OFF   (3*STAGE_SZ)          // 98304: full[3] @ +0, empty[3] @ +32
#define EP_OFF   (MB_OFF + 128)        // per-warp 4KB staging slices
#define SMEM_TOT (EP_OFF + 4*4096)     // 114816 (x2 CTAs = 229632 <= 233472)

__global__ void __launch_bounds__(128,2)
lstm_gemm(const __half* __restrict__ Ah, const __half* __restrict__ Bh,
          const float* __restrict__ hhp, const float* __restrict__ c0l,
          float* __restrict__ outf, __half* __restrict__ outh,
          float* __restrict__ lasth, float* __restrict__ lastc)
{
    extern __shared__ char smem[];
    const uint32_t sb = smem_u32(smem);
    const int tid = threadIdx.x, wid = tid>>5, lane = tid&31;
    const int g = lane>>2, t = lane&3;
    const int wm = wid&1, wn = wid>>1;          // 2 x 2 warp grid, warp tile 64x64
    const int row0 = blockIdx.y*128, ncb = blockIdx.x*128, hbase = ncb>>2;
    const bool tailCTA = (row0 == RR - 128);

    const uint32_t mbF = sb + MB_OFF;        // full[s] at mbF + 8*s
    const uint32_t mbE = sb + MB_OFF + 32;   // empty[s] at mbE + 8*s

    // --- cp.async per-thread constants ---
    const int lr = tid>>3, lc = tid&7;
    const __half* aSrc = Ah + (size_t)(row0+lr)*512 + lc*8;
    const __half* bSrc = Bh + (size_t)(ncb+lr)*512 + lc*8;
    const uint32_t stOff = (uint32_t)(lr*128 + ((lc ^ (lr&7))<<4));

    auto issue = [&](int kc){
        uint32_t base = sb + (kc%3)*STAGE_SZ + stOff;
        const __half* as = aSrc + kc*64;
        const __half* bs = bSrc + kc*64;
#pragma unroll
        for (int j = 0; j < 8; j++) cpa16(base + j*2048, as + j*(16*512));
#pragma unroll
        for (int j = 0; j < 8; j++) cpa16(base + STG_B + j*2048, bs + j*(16*512));
    };

    // init mbarriers (count = 128 thread-arrivals each)
    if (tid == 0){
#pragma unroll
        for (int s = 0; s < 3; s++){ MBAR_INIT(mbF + 8*s, 128); MBAR_INIT(mbE + 8*s, 128); }
    }
    __syncthreads();

    issue(0); CPA_ARRIVE(mbF + 0);
    issue(1); CPA_ARRIVE(mbF + 8);

    float acc[4][8][4];
#pragma unroll
    for (int a = 0; a < 4; a++)
#pragma unroll
        for (int b = 0; b < 8; b++)
#pragma unroll
            for (int c = 0; c < 4; c++) acc[a][b][c] = 0.f;

    // --- ldmatrix per-lane constants ---
    const int lrow = lane&7, grp = lane>>3;
    const uint32_t aBase = (uint32_t)((wm*64 + (grp&1)*8 + lrow)*128);
    const uint32_t bBase = (uint32_t)(STG_B + (wn*64 + (grp>>1)*8 + lrow)*128);
    const int aCsel = grp>>1, bCsel = grp&1;

    auto consume_ks = [&](uint32_t st, int ks){
        const uint32_t va = (uint32_t)(((2*ks + aCsel) ^ lrow) << 4);
        const uint32_t vb = (uint32_t)(((2*ks + bCsel) ^ lrow) << 4);
        uint32_t a[4][4], b[8][2];
#pragma unroll
        for (int mt = 0; mt < 4; mt++)
            ldsm4(a[mt], st + aBase + mt*2048 + va);
#pragma unroll
        for (int pr = 0; pr < 4; pr++){
            uint32_t q[4];
            ldsm4(q, st + bBase + pr*2048 + vb);
            b[pr*2][0] = q[0]; b[pr*2][1] = q[1];
            b[pr*2+1][0] = q[2]; b[pr*2+1][1] = q[3];
        }
#pragma unroll
        for (int mt = 0; mt < 4; mt++)
#pragma unroll
            for (int nt = 0; nt < 8; nt++)
                mma16(acc[mt][nt], a[mt], b[nt]);
    };

    for (int kc = 0; kc < 8; kc++){
        const int s = kc % 3;
        MBAR_WAIT(mbF + 8*s, (kc/3)&1);          // wait stage data (all warps' copies)
        const uint32_t st = sb + s*STAGE_SZ;
        consume_ks(st, 0);
        if (kc < 6){                              // refill 2 ahead
            int k2 = kc + 2, s2 = k2 % 3;
            if (k2 >= 3) MBAR_WAIT(mbE + 8*s2, ((k2/3) - 1)&1);
            issue(k2);
            CPA_ARRIVE(mbF + 8*s2);
        }
        consume_ks(st, 1);
        consume_ks(st, 2);
        consume_ks(st, 3);
        MBAR_ARRIVE(mbE + 8*s);                   // done reading stage s
    }

    // ---- per-warp epilogue: no CTA barriers ----
    float*  epS = (float*) (smem + EP_OFF + wid*4096);   // [64][16] fp32
    __half* epH = (__half*)(smem + EP_OFF + wid*4096);   // [64][16] fp16

#pragma unroll
    for (int mt = 0; mt < 4; mt++){
#pragma unroll
        for (int nt = 0; nt < 8; nt++){
            int rl0 = wm*64 + mt*16 + g;
            int rl1 = rl0 + 8;
            int pl  = wn*64 + nt*8 + 2*t;
            const float2 hbE = *(const float2*)(hhp + (rl0&63)*2048 + ncb + pl);
            const float2 hbO = *(const float2*)(hhp + (rl1&63)*2048 + ncb + pl);
            float d0 = acc[mt][nt][0] + hbE.x;
            float d1 = acc[mt][nt][1] + hbE.y;
            float d2 = acc[mt][nt][2] + hbO.x;
            float d3 = acc[mt][nt][3] + hbO.y;
            float s0 = (t&1) ? d0 : d2;  float r0 = __shfl_xor_sync(0xffffffffu, s0, 1);
            float s1 = (t&1) ? d1 : d3;  float r1 = __shfl_xor_sync(0xffffffffu, s1, 1);
            float ig, fg, gg, og; int rr;
            if (!(t&1)){ ig = d0; fg = d1; gg = r0; og = r1; rr = rl0; }
            else       { ig = r0; fg = r1; gg = d2; og = d3; rr = rl1; }
            int col = nt*2 + (t>>1);               // 0..15 within warp block
            int hl  = wn*16 + col;
            float c0v = c0l[(rr&63)*512 + hbase + hl];
            float tf = tanha(0.5f*fg), ti = tanha(0.5f*ig);
            float tg = tanha(gg),      to = tanha(0.5f*og);
            float cy = (0.5f + 0.5f*tf)*c0v + (0.5f + 0.5f*ti)*tg;
            float hy = (0.5f + 0.5f*to)*tanha(cy);
            if (outf) epS[(rr&63)*16 + col] = hy;
            else      epH[(rr&63)*16 + col] = __float2half_rn(hy);
            if (tailCTA){
                int grow_ = row0 + rr;
                if (grow_ >= RR - BB){
                    int b = grow_ & 63;
                    lasth[b*512 + hbase + hl] = hy;
                    lastc[b*512 + hbase + hl] = cy;
                }
            }
        }
    }
    __syncwarp();

    const int rbase = row0 + wm*64;
    const int cbase = hbase + wn*16;
    if (outf){
#pragma unroll
        for (int j = 0; j < 8; j++){
            int idx = lane + j*32;                 // 0..255
            int r = idx >> 2, c4 = idx & 3;
            float4 v = *(const float4*)(epS + r*16 + c4*4);
            *(float4*)(outf + (size_t)(rbase+r)*512 + cbase + c4*4) = v;
        }
    } else {
#pragma unroll
        for (int j = 0; j < 4; j++){
            int idx = lane + j*32;                 // 0..127
            int r = idx >> 1, hh = idx & 1;
            uint4 v = *(const uint4*)(epH + r*16 + hh*8);
            *(uint4*)(outh + (size_t)(rbase+r)*512 + cbase + hh*8) = v;
        }
    }
}

// ---------------- launch ----------------
extern "C" void kernel_launch(void* const* d_in, const int* in_sizes, int n_in,
                              void* d_out, int out_size)
{
    (void)in_sizes; (void)n_in; (void)out_size;
    const float* x    = (const float*)d_in[0];
    const float* h0   = (const float*)d_in[1];
    const float* c0   = (const float*)d_in[2];
    const float* wih0 = (const float*)d_in[3];
    const float* whh0 = (const float*)d_in[4];
    const float* bih0 = (const float*)d_in[5];
    const float* bhh0 = (const float*)d_in[6];
    const float* wih1 = (const float*)d_in[7];
    const float* whh1 = (const float*)d_in[8];
    const float* bih1 = (const float*)d_in[9];
    const float* bhh1 = (const float*)d_in[10];
    float* out = (float*)d_out;

    static __half* xh_p = nullptr; static __half* hy0h_p = nullptr;
    static __half* wp0_p = nullptr; static __half* wp1_p = nullptr;
    static float* hhp0_p = nullptr; static float* hhp1_p = nullptr;
    if (!xh_p){
        cudaGetSymbolAddress((void**)&xh_p,   g_xh);
        cudaGetSymbolAddress((void**)&hy0h_p, g_hy0h);
        void* wp; cudaGetSymbolAddress(&wp, g_wp);
        wp0_p = (__half*)wp; wp1_p = wp0_p + 2048*512;
        void* hh; cudaGetSymbolAddress(&hh, g_hhp);
        hhp0_p = (float*)hh; hhp1_p = hhp0_p + BB*2048;
        cudaFuncSetAttribute(lstm_gemm, cudaFuncAttributeMaxDynamicSharedMemorySize, SMEM_TOT);
    }

    conv_x<<<(RR*32 + 255)/256, 256>>>(x);
    conv_w<<<dim3(256,2), 256>>>(wih0, wih1);
    prep_hh<<<dim3(128,2), 1024>>>(h0, whh0, bhh0, bih0, whh1, bhh1, bih1);

    // layer 0: A = xh, B = wp0 -> hy0h (fp16), lasth[0], lastc[0]
    lstm_gemm<<<dim3(16,512), 128, SMEM_TOT>>>(xh_p, wp0_p, hhp0_p, c0,
                                               nullptr, hy0h_p,
                                               out + RES, out + RES + 2*(size_t)BH);
    // layer 1: A = hy0h, B = wp1 -> out (fp32), lasth[1], lastc[1]
    lstm_gemm<<<dim3(16,512), 128, SMEM_TOT>>>(hy0h_p, wp1_p, hhp1_p, c0 + BH,
                                               out, nullptr,
                                               out + RES + (size_t)BH, out + RES + 3*(size_t)BH);
}